// round 13
// baseline (speedup 1.0000x reference)
#include <cuda_runtime.h>
#include <math.h>

// Problem constants
#define B_  2
#define T_  2048
#define D_  1024
#define H_  16
#define HD_ 64

// Scratch (allocation-free rule: __device__ globals)
__device__ float g_Q[B_*H_*T_*HD_];   // [B,H,T,HD], pre-scaled by log2e/sqrt(HD)
__device__ float g_K[B_*H_*T_*HD_];   // [B,H,T,HD]
__device__ float g_V[B_*H_*T_*HD_];   // [B,H,T,HD]
__device__ float g_A[B_*T_*D_];       // attention output, [B*T, H*HD]

// Packed fp32x2 ops (Blackwell FFMA2 — only reachable via PTX f32x2)
#define FFMA2(d, a, b, c) \
    asm("fma.rn.f32x2 %0, %1, %2, %3;" : "=l"(d) : "l"(a), "l"(b), "l"(c))
#define MUL2(d, a, b) \
    asm("mul.rn.f32x2 %0, %1, %2;" : "=l"(d) : "l"(a), "l"(b))
// Broadcast one fp32 into both lanes of a 64-bit packed pair
#define PACKDUP(d, s) \
    asm("mov.b64 %0, {%1, %1};" : "=l"(d) : "r"(__float_as_uint(s)))
#define PACKDUP_U(d, s) \
    asm("mov.b64 %0, {%1, %1};" : "=l"(d) : "r"(s))
#define UNPACK2(lo, hi, p) \
    asm("mov.b64 {%0, %1}, %2;" : "=r"(lo), "=r"(hi) : "l"(p))
// Bare MUFU.EX2 (scores are pre-scaled by log2e, so no FMUL needed)
#define EX2(d, x) \
    asm("ex2.approx.f32 %0, %1;" : "=f"(d) : "f"(x))

// cp.async 16B global->shared (sm_80+; maps to LDGSTS-class hardware path)
#define CP_ASYNC16(saddr, gptr) \
    asm volatile("cp.async.cg.shared.global [%0], [%1], 16;" \
                 :: "r"(saddr), "l"(gptr))
#define CP_COMMIT() asm volatile("cp.async.commit_group;")
#define CP_WAIT0()  asm volatile("cp.async.wait_group 0;" ::: "memory")

__device__ __forceinline__ unsigned smem_u32(const void* p) {
    return (unsigned)__cvta_generic_to_shared(p);
}

__device__ __forceinline__ float lo32(unsigned long long p) {
    return __uint_as_float((unsigned)p);
}
__device__ __forceinline__ float hi32(unsigned long long p) {
    return __uint_as_float((unsigned)(p >> 32));
}

struct alignas(16) U128 { unsigned long long u[2]; };

// ---------------------------------------------------------------------------
// GEMM core: 128x128 block tile, BK=16, 256 threads, 8x8 micro-tile,
// double-buffered smem, packed-FFMA2 inner product (acc packed along N).
// B tile copied global->smem via cp.async (no register staging); A tile
// needs a transpose so it stays on the register path. One barrier per step.
// ---------------------------------------------------------------------------
template<int SCATTER>
__device__ __forceinline__ void gemm_body(
    const float* __restrict__ A, const float* __restrict__ B,
    float* __restrict__ C, int M, int N, int K, float alpha)
{
    __shared__ float As[2][16][128];
    __shared__ float Bs[2][16][128];

    const int tid  = threadIdx.x;
    const int bm   = blockIdx.y * 128;
    const int bn   = blockIdx.x * 128;
    const int aRow = tid >> 1;          // 128 rows, 2 threads/row
    const int aCol = (tid & 1) * 8;     // 8 K-cols per thread (2x float4)
    const int bRow = tid >> 5;          // rows bRow and bRow+8
    const int bCol = (tid & 31) * 4;    // float4 along N
    const int tr   = (tid >> 4) * 8;
    const int tc   = (tid & 15) * 8;

    // acc packed along j: accp[i][j2] holds columns (tc+2*j2, tc+2*j2+1)
    unsigned long long accp[8][4];
#pragma unroll
    for (int i = 0; i < 8; i++)
#pragma unroll
        for (int j = 0; j < 4; j++) accp[i][j] = 0ull;

    const float* Aptr = A + (size_t)(bm + aRow) * K + aCol;
    const float* Bptr = B + (size_t)bRow * N + bn + bCol;

    const unsigned bs0[2] = { smem_u32(&Bs[0][bRow][bCol]),
                              smem_u32(&Bs[0][bRow + 8][bCol]) };
    const unsigned bs1[2] = { smem_u32(&Bs[1][bRow][bCol]),
                              smem_u32(&Bs[1][bRow + 8][bCol]) };

    // Preload tile 0: B via cp.async, A via registers (transposed store).
    {
        CP_ASYNC16(bs0[0], Bptr);
        CP_ASYNC16(bs0[1], Bptr + (size_t)8 * N);
        CP_COMMIT();
        float4 av0 = *(const float4*)(Aptr);
        float4 av1 = *(const float4*)(Aptr + 4);
        As[0][aCol + 0][aRow] = av0.x;
        As[0][aCol + 1][aRow] = av0.y;
        As[0][aCol + 2][aRow] = av0.z;
        As[0][aCol + 3][aRow] = av0.w;
        As[0][aCol + 4][aRow] = av1.x;
        As[0][aCol + 5][aRow] = av1.y;
        As[0][aCol + 6][aRow] = av1.z;
        As[0][aCol + 7][aRow] = av1.w;
        CP_WAIT0();
    }
    __syncthreads();

    int buf = 0;
    for (int k0 = 16; k0 <= K; k0 += 16) {
        float4 av0, av1;
        const bool more = (k0 < K);
        if (more) {
            const int nb = buf ^ 1;
            // Safe: all readers of buffer nb passed the previous barrier.
            CP_ASYNC16(nb ? bs1[0] : bs0[0], Bptr + (size_t)k0 * N);
            CP_ASYNC16(nb ? bs1[1] : bs0[1], Bptr + (size_t)(k0 + 8) * N);
            CP_COMMIT();
            av0 = *(const float4*)(Aptr + k0);
            av1 = *(const float4*)(Aptr + k0 + 4);
        }

#pragma unroll
        for (int kk = 0; kk < 16; kk++) {
            float4 ra0 = *(const float4*)&As[buf][kk][tr];
            float4 ra1 = *(const float4*)&As[buf][kk][tr + 4];
            U128 rb0 = *(const U128*)&Bs[buf][kk][tc];      // cols tc..tc+3
            U128 rb1 = *(const U128*)&Bs[buf][kk][tc + 4];  // cols tc+4..tc+7
            float ra[8] = { ra0.x, ra0.y, ra0.z, ra0.w,
                            ra1.x, ra1.y, ra1.z, ra1.w };
#pragma unroll
            for (int i = 0; i < 8; i++) {
                unsigned long long a2;
                PACKDUP(a2, ra[i]);
                FFMA2(accp[i][0], a2, rb0.u[0], accp[i][0]);
                FFMA2(accp[i][1], a2, rb0.u[1], accp[i][1]);
                FFMA2(accp[i][2], a2, rb1.u[0], accp[i][2]);
                FFMA2(accp[i][3], a2, rb1.u[1], accp[i][3]);
            }
        }

        if (more) {
            const int nb = buf ^ 1;
            As[nb][aCol + 0][aRow] = av0.x;
            As[nb][aCol + 1][aRow] = av0.y;
            As[nb][aCol + 2][aRow] = av0.z;
            As[nb][aCol + 3][aRow] = av0.w;
            As[nb][aCol + 4][aRow] = av1.x;
            As[nb][aCol + 5][aRow] = av1.y;
            As[nb][aCol + 6][aRow] = av1.z;
            As[nb][aCol + 7][aRow] = av1.w;
            CP_WAIT0();
            __syncthreads();
            buf = nb;
        }
    }

#pragma unroll
    for (int i = 0; i < 8; i++) {
        const int row = bm + tr + i;
#pragma unroll
        for (int jp = 0; jp < 2; jp++) {     // two float4 stores of 2 pairs each
            const int col = bn + tc + jp * 4;
            const unsigned long long p0 = accp[i][jp * 2];
            const unsigned long long p1 = accp[i][jp * 2 + 1];
            float4 v = make_float4(lo32(p0) * alpha, hi32(p0) * alpha,
                                   lo32(p1) * alpha, hi32(p1) * alpha);
            if (SCATTER) {
                const int b = row >> 11;            // T_ = 2048
                const int t = row & (T_ - 1);
                const int h = col >> 6;             // HD_ = 64
                const int hd = col & (HD_ - 1);
                const size_t idx = (((size_t)(b * H_ + h) * T_ + t) * HD_ + hd);
                *(float4*)&C[idx] = v;
            } else {
                *(float4*)&C[(size_t)row * N + col] = v;
            }
        }
    }
}

// Fused Q/K/V projection: blockIdx.z selects {Q,K,V}. Scatters to [B,H,T,HD].
// Q alpha folds log2e so softmax can use bare EX2: exp(s-m) = 2^(s'-m').
__global__ void __launch_bounds__(256, 2)
qkv_k(const float* __restrict__ Xq, const float* __restrict__ Xkv,
      const float* __restrict__ Wq, const float* __restrict__ Wk,
      const float* __restrict__ Wv,
      float* __restrict__ Qo, float* __restrict__ Ko, float* __restrict__ Vo)
{
    const int z = blockIdx.z;
    const float* A = (z == 0) ? Xq : Xkv;
    const float* W = (z == 0) ? Wq : (z == 1) ? Wk : Wv;
    float*       C = (z == 0) ? Qo : (z == 1) ? Ko : Vo;
    // 1/sqrt(HD) * log2(e) = 0.125 * 1.4426950408889634
    const float alpha = (z == 0) ? 0.18033688011112042f : 1.0f;
    gemm_body<1>(A, W, C, B_ * T_, H_ * HD_, D_, alpha);
}

// Output projection: plain row-major C.
__global__ void __launch_bounds__(256, 2)
oproj_k(const float* __restrict__ A, const float* __restrict__ W,
        float* __restrict__ C)
{
    gemm_body<0>(A, W, C, B_ * T_, D_, H_ * HD_, 1.0f);
}

// ---------------------------------------------------------------------------
// Flash attention, causal. One block per (query-tile 64, b*h).
// 256 threads: ty = tid/16 (4 query rows each), tx = tid%16 (4 cols each).
// Smem planes (stride 66 keeps rows 8B-aligned for LDS.64/STS.64 and gives
// conflict-free column reads in the QK loop):
//   Qs, Ks[2], Vs[2], Ps  — K/V double-buffered so the end-of-iteration
//   WAR barrier disappears: 2 __syncthreads per KV iteration instead of 3.
// Scores are in log2 domain (log2e folded into Q), so softmax uses bare
// MUFU.EX2. Reductions are phase-interleaved for explicit ILP.
// __launch_bounds__(256,2): 512 thr/SM x 128 regs = exactly the 64K-reg file;
// without the pin, >=129 regs silently halves occupancy to 1 CTA/SM.
// ---------------------------------------------------------------------------
#define SM_STRIDE 66
#define PLANE     (64 * SM_STRIDE)
#define SMEM_BYTES (6 * PLANE * 4)

__global__ void __launch_bounds__(256, 2)
attn_k(const float* __restrict__ Q, const float* __restrict__ Kg,
       const float* __restrict__ Vg, float* __restrict__ Out)
{
    extern __shared__ float sm[];
    float (*Qs)[SM_STRIDE]  = (float(*)[SM_STRIDE])sm;
    float (*Ks0)[SM_STRIDE] = (float(*)[SM_STRIDE])(sm + 1 * PLANE);
    float (*Ks1)[SM_STRIDE] = (float(*)[SM_STRIDE])(sm + 2 * PLANE);
    float (*Vs0)[SM_STRIDE] = (float(*)[SM_STRIDE])(sm + 3 * PLANE);
    float (*Vs1)[SM_STRIDE] = (float(*)[SM_STRIDE])(sm + 4 * PLANE);
    float (*Ps)[SM_STRIDE]  = (float(*)[SM_STRIDE])(sm + 5 * PLANE);

    const int tid = threadIdx.x;
    // Longest blocks (largest qb) first: CTAs dispatch roughly in bid order,
    // so this shrinks the last-wave tail of the causal work skew.
    const int qb  = gridDim.x - 1 - blockIdx.x;   // 0..31
    const int bh  = blockIdx.y;                   // 0..31  (b*H + h)
    const int q0  = qb * 64;

    const float* Qb = Q  + (size_t)bh * T_ * HD_;
    const float* Kb = Kg + (size_t)bh * T_ * HD_;
    const float* Vb = Vg + (size_t)bh * T_ * HD_;

    const int ty = tid >> 4, tx = tid & 15;
    const int r0 = ty * 4,  c0 = tx * 4;

    // Per-thread K/V staging coordinates: one row, 16 contiguous floats.
    const int ldRow = tid >> 2;
    const int ldCol = (tid & 3) * 16;

    // Load Q tile (pre-scaled by log2e/sqrt(HD) in projection epilogue)
    {
        const float* src = Qb + (size_t)(q0 + ldRow) * HD_ + ldCol;
#pragma unroll
        for (int i = 0; i < 4; i++) {
            float4 v = *(const float4*)(src + i * 4);
            Qs[ldRow][ldCol + i*4 + 0] = v.x;
            Qs[ldRow][ldCol + i*4 + 1] = v.y;
            Qs[ldRow][ldCol + i*4 + 2] = v.z;
            Qs[ldRow][ldCol + i*4 + 3] = v.w;
        }
    }

    // Preload K/V tile 0 into plane 0 (via registers).
    {
        const float* ks = Kb + (size_t)ldRow * HD_ + ldCol;
        const float* vs = Vb + (size_t)ldRow * HD_ + ldCol;
#pragma unroll
        for (int i = 0; i < 4; i++) {
            float4 kv = *(const float4*)(ks + i * 4);
            float4 vv = *(const float4*)(vs + i * 4);
            *(float2*)&Ks0[ldRow][ldCol + i*4]     = make_float2(kv.x, kv.y);
            *(float2*)&Ks0[ldRow][ldCol + i*4 + 2] = make_float2(kv.z, kv.w);
            *(float2*)&Vs0[ldRow][ldCol + i*4]     = make_float2(vv.x, vv.y);
            *(float2*)&Vs0[ldRow][ldCol + i*4 + 2] = make_float2(vv.z, vv.w);
        }
    }

    float m[4], l[4];
    unsigned long long O2[4][2];    // O packed along j: (c0,c0+1),(c0+2,c0+3)
#pragma unroll
    for (int i = 0; i < 4; i++) {
        m[i] = -INFINITY; l[i] = 0.f;
        O2[i][0] = 0ull; O2[i][1] = 0ull;
    }

    float4 kreg[4], vreg[4];

    for (int kb = 0; kb <= qb; kb++) {
        float (*Kc)[SM_STRIDE] = (kb & 1) ? Ks1 : Ks0;   // current planes
        float (*Vc)[SM_STRIDE] = (kb & 1) ? Vs1 : Vs0;
        float (*Kn)[SM_STRIDE] = (kb & 1) ? Ks0 : Ks1;   // next planes
        float (*Vn)[SM_STRIDE] = (kb & 1) ? Vs0 : Vs1;

        __syncthreads();   // bar1: publish Ks/Vs current plane (and Qs on kb=0)

        // Prefetch next K/V tile into registers during compute.
        const bool more = (kb < qb);
        if (more) {
            const float* ks = Kb + (size_t)((kb + 1) * 64 + ldRow) * HD_ + ldCol;
            const float* vs = Vb + (size_t)((kb + 1) * 64 + ldRow) * HD_ + ldCol;
#pragma unroll
            for (int i = 0; i < 4; i++) {
                kreg[i] = *(const float4*)(ks + i * 4);
                vreg[i] = *(const float4*)(vs + i * 4);
            }
        }

        // S' = (log2e scaled Q) @ K^T, packed along d
        unsigned long long s2[4][4];
#pragma unroll
        for (int i = 0; i < 4; i++)
#pragma unroll
            for (int j = 0; j < 4; j++) s2[i][j] = 0ull;

#pragma unroll
        for (int d = 0; d < 64; d += 2) {
            unsigned long long qa2[4], kv2[4];
#pragma unroll
            for (int i = 0; i < 4; i++)
                qa2[i] = *(const unsigned long long*)&Qs[r0 + i][d];
#pragma unroll
            for (int j = 0; j < 4; j++)
                kv2[j] = *(const unsigned long long*)&Kc[c0 + j][d];
#pragma unroll
            for (int i = 0; i < 4; i++)
#pragma unroll
                for (int j = 0; j < 4; j++)
                    FFMA2(s2[i][j], qa2[i], kv2[j], s2[i][j]);
        }

        // Horizontal reduce lo+hi
        float s[4][4];
#pragma unroll
        for (int i = 0; i < 4; i++)
#pragma unroll
            for (int j = 0; j < 4; j++)
                s[i][j] = lo32(s2[i][j]) + hi32(s2[i][j]);

        // Causal mask on diagonal tile
        if (kb == qb) {
#pragma unroll
            for (int i = 0; i < 4; i++)
#pragma unroll
                for (int j = 0; j < 4; j++)
                    if (c0 + j > r0 + i) s[i][j] = -INFINITY;
        }

        // ---- Online softmax in log2 domain, phase-interleaved ----
        // Phase 1: thread-local maxes.
        float mx[4];
#pragma unroll
        for (int i = 0; i < 4; i++)
            mx[i] = fmaxf(fmaxf(s[i][0], s[i][1]), fmaxf(s[i][2], s[i][3]));
        // Phase 2: butterfly max, 4 independent chains interleaved.
#pragma unroll
        for (int o = 8; o >= 1; o >>= 1) {
#pragma unroll
            for (int i = 0; i < 4; i++)
                mx[i] = fmaxf(mx[i], __shfl_xor_sync(0xffffffffu, mx[i], o));
        }
        // Phase 3: p = 2^(s'-m') via bare MUFU.EX2 + thread-local sums.
        float sum[4], mnew[4];
#pragma unroll
        for (int i = 0; i < 4; i++) {
            mnew[i] = fmaxf(m[i], mx[i]);
            EX2(s[i][0], s[i][0] - mnew[i]);
            EX2(s[i][1], s[i][1] - mnew[i]);
            EX2(s[i][2], s[i][2] - mnew[i]);
            EX2(s[i][3], s[i][3] - mnew[i]);
            sum[i] = (s[i][0] + s[i][1]) + (s[i][2] + s[i][3]);
        }
        // Phase 4: butterfly sum, 4 independent chains interleaved.
#pragma unroll
        for (int o = 8; o >= 1; o >>= 1) {
#pragma unroll
            for (int i = 0; i < 4; i++)
                sum[i] += __shfl_xor_sync(0xffffffffu, sum[i], o);
        }
        // Phase 5: state updates + O rescale (scale = 2^(m_old'-m_new')).
#pragma unroll
        for (int i = 0; i < 4; i++) {
            float scale;
            EX2(scale, m[i] - mnew[i]);
            l[i] = l[i] * scale + sum[i];
            m[i] = mnew[i];
            unsigned long long sc2;
            PACKDUP(sc2, scale);
            MUL2(O2[i][0], O2[i][0], sc2);
            MUL2(O2[i][1], O2[i][1], sc2);
        }

        // Stage P into Ps
#pragma unroll
        for (int i = 0; i < 4; i++)
#pragma unroll
            for (int j = 0; j < 4; j++)
                Ps[r0 + i][c0 + j] = s[i][j];
        __syncthreads();   // bar2: publish Ps; all iter-(kb-1) reads done too

        // Commit staged next-tile K/V to the alternate planes. Safe: their
        // last readers (PV of iter kb-1) finished before bar1 of this iter;
        // their next readers (QK of iter kb+1) wait at bar1 of iter kb+1.
        if (more) {
#pragma unroll
            for (int i = 0; i < 4; i++) {
                *(float2*)&Kn[ldRow][ldCol + i*4]     = make_float2(kreg[i].x, kreg[i].y);
                *(float2*)&Kn[ldRow][ldCol + i*4 + 2] = make_float2(kreg[i].z, kreg[i].w);
                *(float2*)&Vn[ldRow][ldCol + i*4]     = make_float2(vreg[i].x, vreg[i].y);
                *(float2*)&Vn[ldRow][ldCol + i*4 + 2] = make_float2(vreg[i].z, vreg[i].w);
            }
        }

        // O += P @ V. O packed along j. P read as LDS.64 pairs along c,
        // V rows read as LDS.64 pairs along j. Fully unrolled: ptxas can
        // batch LDS issue across c-steps (I$ cost negligible per B300 tiers).
#pragma unroll
        for (int c = 0; c < 64; c += 2) {
            unsigned long long vA0 = *(const unsigned long long*)&Vc[c][c0];
            unsigned long long vA1 = *(const unsigned long long*)&Vc[c][c0 + 2];
            unsigned long long vB0 = *(const unsigned long long*)&Vc[c + 1][c0];
            unsigned long long vB1 = *(const unsigned long long*)&Vc[c + 1][c0 + 2];
#pragma unroll
            for (int i = 0; i < 4; i++) {
                unsigned long long pp =
                    *(const unsigned long long*)&Ps[r0 + i][c];
                unsigned plo, phi;
                UNPACK2(plo, phi, pp);
                unsigned long long pa0, pa1;
                PACKDUP_U(pa0, plo);
                PACKDUP_U(pa1, phi);
                FFMA2(O2[i][0], pa0, vA0, O2[i][0]);
                FFMA2(O2[i][1], pa0, vA1, O2[i][1]);
                FFMA2(O2[i][0], pa1, vB0, O2[i][0]);
                FFMA2(O2[i][1], pa1, vB1, O2[i][1]);
            }
        }
        // no end barrier: next iteration writes only the alternate planes
    }

    // Epilogue: Out layout [B*T, H*HD]
    const int b = bh >> 4;         // H_ = 16
    const int h = bh & (H_ - 1);
#pragma unroll
    for (int i = 0; i < 4; i++) {
        const float inv = 1.0f / l[i];
        float4 v = make_float4(lo32(O2[i][0]) * inv, hi32(O2[i][0]) * inv,
                               lo32(O2[i][1]) * inv, hi32(O2[i][1]) * inv);
        const size_t idx = ((size_t)(b * T_ + q0 + r0 + i)) * D_ + h * HD_ + c0;
        *(float4*)&Out[idx] = v;
    }
}

// ---------------------------------------------------------------------------
// Launch
// ---------------------------------------------------------------------------
extern "C" void kernel_launch(void* const* d_in, const int* in_sizes, int n_in,
                              void* d_out, int out_size)
{
    const float* Xq  = (const float*)d_in[0];
    const float* Xkv = (const float*)d_in[1];
    // d_in[2] = mask: causal, known statically; ignored.
    const float* Wq  = (const float*)d_in[3];
    const float* Wk  = (const float*)d_in[4];
    const float* Wv  = (const float*)d_in[5];
    const float* Wo  = (const float*)d_in[6];
    float* out = (float*)d_out;

    float *Qb, *Kb, *Vb, *Ab;
    cudaGetSymbolAddress((void**)&Qb, g_Q);
    cudaGetSymbolAddress((void**)&Kb, g_K);
    cudaGetSymbolAddress((void**)&Vb, g_V);
    cudaGetSymbolAddress((void**)&Ab, g_A);

    cudaFuncSetAttribute(attn_k, cudaFuncAttributeMaxDynamicSharedMemorySize,
                         SMEM_BYTES);
    // Deterministic carveout: 2 CTAs x 99KB smem need the max smem split.
    cudaFuncSetAttribute(attn_k,
                         cudaFuncAttributePreferredSharedMemoryCarveout, 100);

    dim3 gQKV(H_ * HD_ / 128, B_ * T_ / 128, 3);   // (8, 32, 3)
    qkv_k<<<gQKV, 256>>>(Xq, Xkv, Wq, Wk, Wv, Qb, Kb, Vb);

    dim3 gAttn(T_ / 64, B_ * H_);                  // (32, 32)
    attn_k<<<gAttn, 256, SMEM_BYTES>>>(Qb, Kb, Vb, Ab);

    dim3 gO(D_ / 128, B_ * T_ / 128);              // (8, 32)
    oproj_k<<<gO, 256>>>(Ab, Wo, out);
}

// round 15
// speedup vs baseline: 1.0658x; 1.0658x over previous
#include <cuda_runtime.h>
#include <math.h>

// Problem constants
#define B_  2
#define T_  2048
#define D_  1024
#define H_  16
#define HD_ 64

// Scratch (allocation-free rule: __device__ globals)
__device__ float g_Q[B_*H_*T_*HD_];   // [B,H,T,HD], pre-scaled by log2e/sqrt(HD)
__device__ float g_K[B_*H_*T_*HD_];   // [B,H,T,HD]
__device__ float g_V[B_*H_*T_*HD_];   // [B,H,T,HD]
__device__ float g_A[B_*T_*D_];       // attention output, [B*T, H*HD]

// Packed fp32x2 ops (Blackwell FFMA2) — used by the attention kernel
#define FFMA2(d, a, b, c) \
    asm("fma.rn.f32x2 %0, %1, %2, %3;" : "=l"(d) : "l"(a), "l"(b), "l"(c))
#define MUL2(d, a, b) \
    asm("mul.rn.f32x2 %0, %1, %2;" : "=l"(d) : "l"(a), "l"(b))
#define PACKDUP(d, s) \
    asm("mov.b64 %0, {%1, %1};" : "=l"(d) : "r"(__float_as_uint(s)))
#define PACKDUP_U(d, s) \
    asm("mov.b64 %0, {%1, %1};" : "=l"(d) : "r"(s))
#define UNPACK2(lo, hi, p) \
    asm("mov.b64 {%0, %1}, %2;" : "=r"(lo), "=r"(hi) : "l"(p))
#define EX2(d, x) \
    asm("ex2.approx.f32 %0, %1;" : "=f"(d) : "f"(x))

__device__ __forceinline__ float lo32(unsigned long long p) {
    return __uint_as_float((unsigned)p);
}
__device__ __forceinline__ float hi32(unsigned long long p) {
    return __uint_as_float((unsigned)(p >> 32));
}

// tf32 helpers
__device__ __forceinline__ unsigned f2tf32(float x) {
    unsigned r; asm("cvt.rna.tf32.f32 %0, %1;" : "=r"(r) : "f"(x)); return r;
}

// mma.sync m16n8k8 tf32: D = A*B + D (fp32 accumulate)
#define MMA_TF32(d, a, b) \
    asm("mma.sync.aligned.m16n8k8.row.col.f32.tf32.tf32.f32 " \
        "{%0,%1,%2,%3}, {%4,%5,%6,%7}, {%8,%9}, {%0,%1,%2,%3};" \
        : "+f"((d)[0]), "+f"((d)[1]), "+f"((d)[2]), "+f"((d)[3]) \
        : "r"((a)[0]), "r"((a)[1]), "r"((a)[2]), "r"((a)[3]), \
          "r"((b)[0]), "r"((b)[1]))

// ---------------------------------------------------------------------------
// Tensor-core GEMM (tf32x3): C[M,N] = alpha * A[M,K] @ B[K,N], fp32-accurate.
// x = hi + lo (both tf32); A@B ~= Ahi@Bhi + Ahi@Blo + Alo@Bhi (lo*lo ~2^-22).
// 128x128x16 tile, 256 threads = 8 warps in 2(M)x4(N), warp tile 64x32.
// Smem tiles stored [k][x] with row stride 136 words (=8 mod 32) so fragment
// loads hit bank (8*tg + g + const) — a permutation of the warp, conflict-free.
// hi/lo conversion happens ONCE per element at the staging step.
// ---------------------------------------------------------------------------
#define BM 128
#define BN 128
#define BK 16
#define TSTR 136
#define TILE_W (BK * TSTR)        // 2176 words per tile
#define BUF_W  (4 * TILE_W)       // Ahi, Alo, Bhi, Blo
#define GEMM_SMEM_BYTES (2 * BUF_W * 4)   // 69632 B (double-buffered)

template<int SCATTER>
__device__ __forceinline__ void gemm_body(
    const float* __restrict__ A, const float* __restrict__ B,
    float* __restrict__ C, int M, int N, int K, float alpha,
    unsigned* sw)
{
    const int tid  = threadIdx.x;
    const int bm   = blockIdx.y * BM;
    const int bn   = blockIdx.x * BN;
    const int warp = tid >> 5, lane = tid & 31;
    const int g  = lane >> 2, tg = lane & 3;
    const int wm = (warp >> 2) * 64;   // warp M origin within tile
    const int wn = (warp & 3) * 32;    // warp N origin within tile

    // Staging assignment: 2 float4 of A and 2 of B per thread per stage.
    int aRow[2], aCol[2], bRow[2], bCol[2];
#pragma unroll
    for (int i = 0; i < 2; i++) {
        const int fa = tid * 2 + i;
        aRow[i] = fa >> 2;        aCol[i] = (fa & 3) * 4;
        bRow[i] = fa >> 5;        bCol[i] = (fa & 31) * 4;
    }

    float acc[4][4][4];
#pragma unroll
    for (int mt = 0; mt < 4; mt++)
#pragma unroll
        for (int nt = 0; nt < 4; nt++)
#pragma unroll
            for (int r = 0; r < 4; r++) acc[mt][nt][r] = 0.f;

    // Stage tile k0 into buffer buf (load fp32, split hi/lo, store to smem).
    auto stage = [&](int k0, int buf, const float4* avp, const float4* bvp) {
        unsigned* Ahi = sw + buf * BUF_W;
        unsigned* Alo = Ahi + TILE_W;
        unsigned* Bhi = Alo + TILE_W;
        unsigned* Blo = Bhi + TILE_W;
#pragma unroll
        for (int i = 0; i < 2; i++) {
            const float4 av = avp[i];
            const float a4[4] = { av.x, av.y, av.z, av.w };
#pragma unroll
            for (int j = 0; j < 4; j++) {
                const unsigned hi = f2tf32(a4[j]);
                const unsigned lo = f2tf32(a4[j] - __uint_as_float(hi));
                const int idx = (aCol[i] + j) * TSTR + aRow[i];
                Ahi[idx] = hi; Alo[idx] = lo;
            }
            const float4 bv = bvp[i];
            const float b4[4] = { bv.x, bv.y, bv.z, bv.w };
            uint4 h, l;
            h.x = f2tf32(b4[0]); l.x = f2tf32(b4[0] - __uint_as_float(h.x));
            h.y = f2tf32(b4[1]); l.y = f2tf32(b4[1] - __uint_as_float(h.y));
            h.z = f2tf32(b4[2]); l.z = f2tf32(b4[2] - __uint_as_float(h.z));
            h.w = f2tf32(b4[3]); l.w = f2tf32(b4[3] - __uint_as_float(h.w));
            const int idx = bRow[i] * TSTR + bCol[i];   // 16B aligned
            *(uint4*)&Bhi[idx] = h;
            *(uint4*)&Blo[idx] = l;
        }
    };

    auto load_gl = [&](int k0, float4* avp, float4* bvp) {
#pragma unroll
        for (int i = 0; i < 2; i++) {
            avp[i] = *(const float4*)(A + (size_t)(bm + aRow[i]) * K + k0 + aCol[i]);
            bvp[i] = *(const float4*)(B + (size_t)(k0 + bRow[i]) * N + bn + bCol[i]);
        }
    };

    // Preload stage 0
    {
        float4 av[2], bv[2];
        load_gl(0, av, bv);
        stage(0, 0, av, bv);
    }
    __syncthreads();

    int buf = 0;
    for (int k0 = BK; k0 <= K; k0 += BK) {
        const bool more = (k0 < K);
        float4 av[2], bv[2];
        if (more) load_gl(k0, av, bv);

        const unsigned* Ahi = sw + buf * BUF_W;
        const unsigned* Alo = Ahi + TILE_W;
        const unsigned* Bhi = Alo + TILE_W;
        const unsigned* Blo = Bhi + TILE_W;

#pragma unroll
        for (int kk = 0; kk < BK; kk += 8) {
            const int r0 = (kk + tg) * TSTR;
            const int r1 = (kk + tg + 4) * TSTR;
            unsigned ah[4][4], bh[4][2];
#pragma unroll
            for (int mt = 0; mt < 4; mt++) {
                const int m = wm + mt * 16 + g;
                ah[mt][0] = Ahi[r0 + m];
                ah[mt][1] = Ahi[r0 + m + 8];
                ah[mt][2] = Ahi[r1 + m];
                ah[mt][3] = Ahi[r1 + m + 8];
            }
#pragma unroll
            for (int nt = 0; nt < 4; nt++) {
                const int n = wn + nt * 8 + g;
                bh[nt][0] = Bhi[r0 + n];
                bh[nt][1] = Bhi[r1 + n];
            }
            // hi * hi
#pragma unroll
            for (int mt = 0; mt < 4; mt++)
#pragma unroll
                for (int nt = 0; nt < 4; nt++)
                    MMA_TF32(acc[mt][nt], ah[mt], bh[nt]);
            // hi * lo
            {
                unsigned bl[4][2];
#pragma unroll
                for (int nt = 0; nt < 4; nt++) {
                    const int n = wn + nt * 8 + g;
                    bl[nt][0] = Blo[r0 + n];
                    bl[nt][1] = Blo[r1 + n];
                }
#pragma unroll
                for (int mt = 0; mt < 4; mt++)
#pragma unroll
                    for (int nt = 0; nt < 4; nt++)
                        MMA_TF32(acc[mt][nt], ah[mt], bl[nt]);
            }
            // lo * hi
            {
                unsigned al[4][4];
#pragma unroll
                for (int mt = 0; mt < 4; mt++) {
                    const int m = wm + mt * 16 + g;
                    al[mt][0] = Alo[r0 + m];
                    al[mt][1] = Alo[r0 + m + 8];
                    al[mt][2] = Alo[r1 + m];
                    al[mt][3] = Alo[r1 + m + 8];
                }
#pragma unroll
                for (int mt = 0; mt < 4; mt++)
#pragma unroll
                    for (int nt = 0; nt < 4; nt++)
                        MMA_TF32(acc[mt][nt], al[mt], bh[nt]);
            }
        }

        if (more) {
            stage(k0, buf ^ 1, av, bv);
            __syncthreads();
            buf ^= 1;
        }
    }

    // Epilogue. c0,c1: row=g, cols 2tg,2tg+1; c2,c3: row=g+8 same cols.
#pragma unroll
    for (int mt = 0; mt < 4; mt++) {
        const int row0 = bm + wm + mt * 16 + g;
#pragma unroll
        for (int nt = 0; nt < 4; nt++) {
            const int col = bn + wn + nt * 8 + 2 * tg;
            float2 v0 = make_float2(acc[mt][nt][0] * alpha, acc[mt][nt][1] * alpha);
            float2 v1 = make_float2(acc[mt][nt][2] * alpha, acc[mt][nt][3] * alpha);
            if (SCATTER) {
                const int h  = col >> 6;          // HD_ = 64
                const int hd = col & (HD_ - 1);
#pragma unroll
                for (int p = 0; p < 2; p++) {
                    const int row = row0 + p * 8;
                    const int b = row >> 11;      // T_ = 2048
                    const int t = row & (T_ - 1);
                    const size_t idx = (((size_t)(b * H_ + h) * T_ + t) * HD_ + hd);
                    *(float2*)&C[idx] = p ? v1 : v0;
                }
            } else {
                *(float2*)&C[(size_t)row0 * N + col]       = v0;
                *(float2*)&C[(size_t)(row0 + 8) * N + col] = v1;
            }
        }
    }
}

// Fused Q/K/V projection: blockIdx.z selects {Q,K,V}. Scatters to [B,H,T,HD].
// Q alpha folds log2e so softmax can use bare EX2.
__global__ void __launch_bounds__(256, 2)
qkv_k(const float* __restrict__ Xq, const float* __restrict__ Xkv,
      const float* __restrict__ Wq, const float* __restrict__ Wk,
      const float* __restrict__ Wv,
      float* __restrict__ Qo, float* __restrict__ Ko, float* __restrict__ Vo)
{
    extern __shared__ unsigned sw[];
    const int z = blockIdx.z;
    const float* A = (z == 0) ? Xq : Xkv;
    const float* W = (z == 0) ? Wq : (z == 1) ? Wk : Wv;
    float*       C = (z == 0) ? Qo : (z == 1) ? Ko : Vo;
    // 1/sqrt(HD) * log2(e)
    const float alpha = (z == 0) ? 0.18033688011112042f : 1.0f;
    gemm_body<1>(A, W, C, B_ * T_, H_ * HD_, D_, alpha, sw);
}

__global__ void __launch_bounds__(256, 2)
oproj_k(const float* __restrict__ A, const float* __restrict__ W,
        float* __restrict__ C)
{
    extern __shared__ unsigned sw[];
    gemm_body<0>(A, W, C, B_ * T_, D_, H_ * HD_, 1.0f, sw);
}

// ---------------------------------------------------------------------------
// Flash attention (unchanged from the passing R13 kernel).
// ---------------------------------------------------------------------------
#define SM_STRIDE 66
#define PLANE     (64 * SM_STRIDE)
#define SMEM_BYTES (6 * PLANE * 4)

__global__ void __launch_bounds__(256, 2)
attn_k(const float* __restrict__ Q, const float* __restrict__ Kg,
       const float* __restrict__ Vg, float* __restrict__ Out)
{
    extern __shared__ float sm[];
    float (*Qs)[SM_STRIDE]  = (float(*)[SM_STRIDE])sm;
    float (*Ks0)[SM_STRIDE] = (float(*)[SM_STRIDE])(sm + 1 * PLANE);
    float (*Ks1)[SM_STRIDE] = (float(*)[SM_STRIDE])(sm + 2 * PLANE);
    float (*Vs0)[SM_STRIDE] = (float(*)[SM_STRIDE])(sm + 3 * PLANE);
    float (*Vs1)[SM_STRIDE] = (float(*)[SM_STRIDE])(sm + 4 * PLANE);
    float (*Ps)[SM_STRIDE]  = (float(*)[SM_STRIDE])(sm + 5 * PLANE);

    const int tid = threadIdx.x;
    const int qb  = gridDim.x - 1 - blockIdx.x;   // longest blocks first
    const int bh  = blockIdx.y;
    const int q0  = qb * 64;

    const float* Qb = Q  + (size_t)bh * T_ * HD_;
    const float* Kb = Kg + (size_t)bh * T_ * HD_;
    const float* Vb = Vg + (size_t)bh * T_ * HD_;

    const int ty = tid >> 4, tx = tid & 15;
    const int r0 = ty * 4,  c0 = tx * 4;
    const int ldRow = tid >> 2;
    const int ldCol = (tid & 3) * 16;

    {
        const float* src = Qb + (size_t)(q0 + ldRow) * HD_ + ldCol;
#pragma unroll
        for (int i = 0; i < 4; i++) {
            float4 v = *(const float4*)(src + i * 4);
            Qs[ldRow][ldCol + i*4 + 0] = v.x;
            Qs[ldRow][ldCol + i*4 + 1] = v.y;
            Qs[ldRow][ldCol + i*4 + 2] = v.z;
            Qs[ldRow][ldCol + i*4 + 3] = v.w;
        }
    }
    {
        const float* ks = Kb + (size_t)ldRow * HD_ + ldCol;
        const float* vs = Vb + (size_t)ldRow * HD_ + ldCol;
#pragma unroll
        for (int i = 0; i < 4; i++) {
            float4 kv = *(const float4*)(ks + i * 4);
            float4 vv = *(const float4*)(vs + i * 4);
            *(float2*)&Ks0[ldRow][ldCol + i*4]     = make_float2(kv.x, kv.y);
            *(float2*)&Ks0[ldRow][ldCol + i*4 + 2] = make_float2(kv.z, kv.w);
            *(float2*)&Vs0[ldRow][ldCol + i*4]     = make_float2(vv.x, vv.y);
            *(float2*)&Vs0[ldRow][ldCol + i*4 + 2] = make_float2(vv.z, vv.w);
        }
    }

    float m[4], l[4];
    unsigned long long O2[4][2];
#pragma unroll
    for (int i = 0; i < 4; i++) {
        m[i] = -INFINITY; l[i] = 0.f;
        O2[i][0] = 0ull; O2[i][1] = 0ull;
    }

    float4 kreg[4], vreg[4];

    for (int kb = 0; kb <= qb; kb++) {
        float (*Kc)[SM_STRIDE] = (kb & 1) ? Ks1 : Ks0;
        float (*Vc)[SM_STRIDE] = (kb & 1) ? Vs1 : Vs0;
        float (*Kn)[SM_STRIDE] = (kb & 1) ? Ks0 : Ks1;
        float (*Vn)[SM_STRIDE] = (kb & 1) ? Vs0 : Vs1;

        __syncthreads();   // bar1

        const bool more = (kb < qb);
        if (more) {
            const float* ks = Kb + (size_t)((kb + 1) * 64 + ldRow) * HD_ + ldCol;
            const float* vs = Vb + (size_t)((kb + 1) * 64 + ldRow) * HD_ + ldCol;
#pragma unroll
            for (int i = 0; i < 4; i++) {
                kreg[i] = *(const float4*)(ks + i * 4);
                vreg[i] = *(const float4*)(vs + i * 4);
            }
        }

        unsigned long long s2[4][4];
#pragma unroll
        for (int i = 0; i < 4; i++)
#pragma unroll
            for (int j = 0; j < 4; j++) s2[i][j] = 0ull;

#pragma unroll
        for (int d = 0; d < 64; d += 2) {
            unsigned long long qa2[4], kv2[4];
#pragma unroll
            for (int i = 0; i < 4; i++)
                qa2[i] = *(const unsigned long long*)&Qs[r0 + i][d];
#pragma unroll
            for (int j = 0; j < 4; j++)
                kv2[j] = *(const unsigned long long*)&Kc[c0 + j][d];
#pragma unroll
            for (int i = 0; i < 4; i++)
#pragma unroll
                for (int j = 0; j < 4; j++)
                    FFMA2(s2[i][j], qa2[i], kv2[j], s2[i][j]);
        }

        float s[4][4];
#pragma unroll
        for (int i = 0; i < 4; i++)
#pragma unroll
            for (int j = 0; j < 4; j++)
                s[i][j] = lo32(s2[i][j]) + hi32(s2[i][j]);

        if (kb == qb) {
#pragma unroll
            for (int i = 0; i < 4; i++)
#pragma unroll
                for (int j = 0; j < 4; j++)
                    if (c0 + j > r0 + i) s[i][j] = -INFINITY;
        }

        float mx[4];
#pragma unroll
        for (int i = 0; i < 4; i++)
            mx[i] = fmaxf(fmaxf(s[i][0], s[i][1]), fmaxf(s[i][2], s[i][3]));
#pragma unroll
        for (int o = 8; o >= 1; o >>= 1) {
#pragma unroll
            for (int i = 0; i < 4; i++)
                mx[i] = fmaxf(mx[i], __shfl_xor_sync(0xffffffffu, mx[i], o));
        }
        float sum[4], mnew[4];
#pragma unroll
        for (int i = 0; i < 4; i++) {
            mnew[i] = fmaxf(m[i], mx[i]);
            EX2(s[i][0], s[i][0] - mnew[i]);
            EX2(s[i][1], s[i][1] - mnew[i]);
            EX2(s[i][2], s[i][2] - mnew[i]);
            EX2(s[i][3], s[i][3] - mnew[i]);
            sum[i] = (s[i][0] + s[i][1]) + (s[i][2] + s[i][3]);
        }
#pragma unroll
        for (int o = 8; o >= 1; o >>= 1) {
#pragma unroll
            for (int i = 0; i < 4; i++)
                sum[i] += __shfl_xor_sync(0xffffffffu, sum[i], o);
        }
#pragma unroll
        for (int i = 0; i < 4; i++) {
            float scale;
            EX2(scale, m[i] - mnew[i]);
            l[i] = l[i] * scale + sum[i];
            m[i] = mnew[i];
            unsigned long long sc2;
            PACKDUP(sc2, scale);
            MUL2(O2[i][0], O2[i][0], sc2);
            MUL2(O2[i][1], O2[i][1], sc2);
        }

#pragma unroll
        for (int i = 0; i < 4; i++)
#pragma unroll
            for (int j = 0; j < 4; j++)
                Ps[r0 + i][c0 + j] = s[i][j];
        __syncthreads();   // bar2

        if (more) {
#pragma unroll
            for (int i = 0; i < 4; i++) {
                *(float2*)&Kn[ldRow][ldCol + i*4]     = make_float2(kreg[i].x, kreg[i].y);
                *(float2*)&Kn[ldRow][ldCol + i*4 + 2] = make_float2(kreg[i].z, kreg[i].w);
                *(float2*)&Vn[ldRow][ldCol + i*4]     = make_float2(vreg[i].x, vreg[i].y);
                *(float2*)&Vn[ldRow][ldCol + i*4 + 2] = make_float2(vreg[i].z, vreg[i].w);
            }
        }

#pragma unroll
        for (int c = 0; c < 64; c += 2) {
            unsigned long long vA0 = *(const unsigned long long*)&Vc[c][c0];
            unsigned long long vA1 = *(const unsigned long long*)&Vc[c][c0 + 2];
            unsigned long long vB0 = *(const unsigned long long*)&Vc[c + 1][c0];
            unsigned long long vB1 = *(const unsigned long long*)&Vc[c + 1][c0 + 2];
#pragma unroll
            for (int i = 0; i < 4; i++) {
                unsigned long long pp =
                    *(const unsigned long long*)&Ps[r0 + i][c];
                unsigned plo, phi;
                UNPACK2(plo, phi, pp);
                unsigned long long pa0, pa1;
                PACKDUP_U(pa0, plo);
                PACKDUP_U(pa1, phi);
                FFMA2(O2[i][0], pa0, vA0, O2[i][0]);
                FFMA2(O2[i][1], pa0, vA1, O2[i][1]);
                FFMA2(O2[i][0], pa1, vB0, O2[i][0]);
                FFMA2(O2[i][1], pa1, vB1, O2[i][1]);
            }
        }
    }

    const int b = bh >> 4;
    const int h = bh & (H_ - 1);
#pragma unroll
    for (int i = 0; i < 4; i++) {
        const float inv = 1.0f / l[i];
        float4 v = make_float4(lo32(O2[i][0]) * inv, hi32(O2[i][0]) * inv,
                               lo32(O2[i][1]) * inv, hi32(O2[i][1]) * inv);
        const size_t idx = ((size_t)(b * T_ + q0 + r0 + i)) * D_ + h * HD_ + c0;
        *(float4*)&Out[idx] = v;
    }
}

// ---------------------------------------------------------------------------
// Launch
// ---------------------------------------------------------------------------
extern "C" void kernel_launch(void* const* d_in, const int* in_sizes, int n_in,
                              void* d_out, int out_size)
{
    const float* Xq  = (const float*)d_in[0];
    const float* Xkv = (const float*)d_in[1];
    // d_in[2] = mask: causal, known statically; ignored.
    const float* Wq  = (const float*)d_in[3];
    const float* Wk  = (const float*)d_in[4];
    const float* Wv  = (const float*)d_in[5];
    const float* Wo  = (const float*)d_in[6];
    float* out = (float*)d_out;

    float *Qb, *Kb, *Vb, *Ab;
    cudaGetSymbolAddress((void**)&Qb, g_Q);
    cudaGetSymbolAddress((void**)&Kb, g_K);
    cudaGetSymbolAddress((void**)&Vb, g_V);
    cudaGetSymbolAddress((void**)&Ab, g_A);

    cudaFuncSetAttribute(qkv_k, cudaFuncAttributeMaxDynamicSharedMemorySize,
                         GEMM_SMEM_BYTES);
    cudaFuncSetAttribute(oproj_k, cudaFuncAttributeMaxDynamicSharedMemorySize,
                         GEMM_SMEM_BYTES);
    cudaFuncSetAttribute(qkv_k,
                         cudaFuncAttributePreferredSharedMemoryCarveout, 100);
    cudaFuncSetAttribute(oproj_k,
                         cudaFuncAttributePreferredSharedMemoryCarveout, 100);
    cudaFuncSetAttribute(attn_k, cudaFuncAttributeMaxDynamicSharedMemorySize,
                         SMEM_BYTES);
    cudaFuncSetAttribute(attn_k,
                         cudaFuncAttributePreferredSharedMemoryCarveout, 100);

    dim3 gQKV(H_ * HD_ / BN, B_ * T_ / BM, 3);     // (8, 32, 3)
    qkv_k<<<gQKV, 256, GEMM_SMEM_BYTES>>>(Xq, Xkv, Wq, Wk, Wv, Qb, Kb, Vb);

    dim3 gAttn(T_ / 64, B_ * H_);                  // (32, 32)
    attn_k<<<gAttn, 256, SMEM_BYTES>>>(Qb, Kb, Vb, Ab);

    dim3 gO(D_ / BN, B_ * T_ / BM);                // (8, 32)
    oproj_k<<<gO, 256, GEMM_SMEM_BYTES>>>(Ab, Wo, out);
}